// round 15
// baseline (speedup 1.0000x reference)
#include <cuda_runtime.h>

#define BB 128
typedef unsigned long long u64;

__device__ __forceinline__ u64 pack2(float x, float y){
    u64 r; asm("mov.b64 %0,{%1,%2};" : "=l"(r) : "f"(x), "f"(y)); return r;
}
__device__ __forceinline__ void unpack2(u64 a, float& x, float& y){
    asm("mov.b64 {%0,%1},%2;" : "=f"(x), "=f"(y) : "l"(a));
}
__device__ __forceinline__ u64 fma2(u64 a, u64 b, u64 c){
    u64 d; asm("fma.rn.f32x2 %0,%1,%2,%3;" : "=l"(d) : "l"(a), "l"(b), "l"(c)); return d;
}
__device__ __forceinline__ float fast_tanh(float x){
    float e = __expf(2.0f * x);
    return 1.0f - __fdividef(2.0f, e + 1.0f);
}

// Folded score matrices (recomputed every launch by gg_kernel -> deterministic)
__device__ float Gd [128 * 128];   // Wq  @ Wk^T
__device__ float God[128 * 128];   // Wqo @ Wko^T

// ============ Precompute kernel: verbatim from passing R14 ============
#define GG_AT   (128 * 18)
#define GG_BT   (128 * 66)
#define GG_SMEM ((GG_AT + 2 * GG_BT) * sizeof(float))

__global__ __launch_bounds__(512, 1)
void gg_kernel(const float* __restrict__ Wq,  const float* __restrict__ Wk,
               const float* __restrict__ Wqo, const float* __restrict__ Wko)
{
    cudaTriggerProgrammaticLaunchCompletion();

    extern __shared__ float gg_sm[];
    float* aT  = gg_sm;
    float* bTa = gg_sm + GG_AT;
    float* bTb = bTa + GG_BT;

    const int tid = threadIdx.x;
    const int cta = blockIdx.x;          // 0..15
    const bool second = cta >= 8;
    const int d0 = (cta & 7) * 16;
    const float* Wa = second ? Wqo : Wq;
    const float* Wb = second ? Wko : Wk;
    float* Gout = second ? God : Gd;

    for (int idx = tid; idx < 16 * 128; idx += 512) {
        int r = idx >> 7, a = idx & 127;
        aT[a * 18 + r] = Wa[(d0 + r) * 128 + a];
    }
    for (int idx = tid; idx < 64 * 128; idx += 512) {
        int e = idx >> 7, a = idx & 127;
        bTa[a * 66 + e] = Wb[e * 128 + a];
        bTb[a * 66 + e] = Wb[(64 + e) * 128 + a];
    }
    __syncthreads();

    const int half = tid >> 8;
    const int t2   = tid & 255;
    const int e2 = t2 & 31;
    const int rg = t2 >> 5;
    const float* bT = half ? bTb : bTa;
    const int e0 = half * 64;

    u64 acc0 = 0ull, acc1 = 0ull;
#pragma unroll 4
    for (int a = 0; a < 128; a++) {
        const u64 we = *reinterpret_cast<const u64*>(&bT[a * 66 + 2 * e2]);
        const float2 ar = *reinterpret_cast<const float2*>(&aT[a * 18 + 2 * rg]);
        acc0 = fma2(pack2(ar.x, ar.x), we, acc0);
        acc1 = fma2(pack2(ar.y, ar.y), we, acc1);
    }
    float x0, x1, y0, y1;
    unpack2(acc0, x0, x1);
    unpack2(acc1, y0, y1);
    float* g0 = Gout + (d0 + 2 * rg) * 128 + e0 + 2 * e2;
    *reinterpret_cast<float2*>(g0)       = make_float2(x0, x1);
    *reinterpret_cast<float2*>(g0 + 128) = make_float2(y0, y1);
}

#define ST_T16 20
#define ST_T32 36
#define ST_RM  132
#define ST_PX  66

struct Smem {
    float sT    [128 * ST_T16];
    float oaoT  [136 * ST_T32];
    float act   [16 * 8];
    float pol   [16 * 8];
    float YTa   [128 * ST_T16];  // Y kh0, then combined
    float YTb   [128 * ST_T16];  // Y kh1
    float YoTa  [128 * ST_T16];
    float YoTb  [128 * ST_T16];
    float t0    [16 * ST_RM];    // s@Wv k-quarters
    float t1    [16 * ST_RM];
    float t2    [16 * ST_RM];
    float t3    [16 * ST_RM];
    float avoTa [128 * ST_T32];  // Wvo kh0 raw, then tanh(combined)
    float avoTb [128 * ST_T32];  // kh1 raw
    float avactT[128 * ST_T16];
    float deltaT[128 * ST_T16];
    float w     [256];
    float wo    [512];
    float P     [16 * ST_PX];
    float v     [16 * ST_PX];
    float X     [32 * ST_PX];    // kh0
    float X2    [32 * ST_PX];    // kh1
    float u     [16 * ST_PX];
    float w2v   [64];
};

__global__ __launch_bounds__(768, 1)
void critic_kernel(const float* __restrict__ states,
                   const float* __restrict__ policies,
                   const float* __restrict__ actions,
                   const float* __restrict__ states_o,
                   const float* __restrict__ actions_o,
                   const float* __restrict__ Wv,
                   const float* __restrict__ Wvo,
                   const float* __restrict__ W1,  const float* __restrict__ W2,
                   float* __restrict__ out_value,
                   float* __restrict__ out_w,
                   float* __restrict__ out_wo)
{
    extern __shared__ unsigned char smem_raw[];
    Smem& sm = *reinterpret_cast<Smem*>(smem_raw);

    const int b    = blockIdx.x;
    const int tid  = threadIdx.x;
    const int warp = tid >> 5;
    const int lane = tid & 31;

    // ---------- Stage-1 config (24 warps) ----------
    // warps 0-7 : Y/Yo via G/Go (gated): mat x colh x kh
    // warps 8-15: Wv: colh x k-quarter  -> t0..t3
    // warps 16-23: Wvo: colh x rowgroup(16) x kh -> avoTa/avoTb (raw)
    int r0 = 0, kbeg, kend, koff, col, cls;
    const float* Wm;
    const float* Abase;
    int astride;
    float* outp = nullptr;   // cls0/cls2 transposed output base
    float* tq   = nullptr;   // cls1 row-major output
    if (warp < 8) {
        cls = 0;
        const int mat = warp >> 2;
        const int sub = warp & 3;
        const int kh = sub >> 1, colh = sub & 1;
        col = colh * 64 + lane * 2;
        kbeg = kh * 64; kend = kbeg + 64;
        koff = kbeg + ((warp * 8) & 63);
        Wm = (mat ? God : Gd) + col;
        Abase = sm.sT; astride = ST_T16;
        outp = mat ? (kh ? sm.YoTb : sm.YoTa) : (kh ? sm.YTb : sm.YTa);
    } else if (warp < 16) {
        cls = 1;
        const int sub = warp - 8;
        const int colh = sub & 1, kq = sub >> 1;
        col = colh * 64 + lane * 2;
        kbeg = kq * 32; kend = kbeg + 32;
        koff = kbeg + ((warp * 8) & 31);
        Wm = Wv + col;
        Abase = sm.sT; astride = ST_T16;
        tq = (kq == 0 ? sm.t0 : kq == 1 ? sm.t1 : kq == 2 ? sm.t2 : sm.t3);
    } else {
        cls = 2;
        const int wrp = warp - 16;
        const int colh = wrp & 1, rg = (wrp >> 1) & 1, kh = wrp >> 2;
        col = colh * 64 + lane * 2;
        r0 = rg * 16;
        kbeg = kh * 68; kend = kbeg + 68;
        koff = kbeg + ((wrp * 8) & 63);
        Wm = Wvo + col;
        Abase = sm.oaoT; astride = ST_T32;
        outp = kh ? sm.avoTb : sm.avoTa;
    }
    auto ldw = [&](int k){ return *reinterpret_cast<const float2*>(Wm + k * 128); };

    // ---------- Stage 0: load + transpose inputs (threads 0-511, as proven) ----------
    if (tid < 512) {
        const int k  = tid & 127;
        const int g  = tid >> 7;
        const int rr = g * 4;
        const float* S = states + (size_t)b * 16 * 128;
        {
            float a0 = S[(rr + 0) * 128 + k];
            float a1 = S[(rr + 1) * 128 + k];
            float a2 = S[(rr + 2) * 128 + k];
            float a3 = S[(rr + 3) * 128 + k];
            *reinterpret_cast<float4*>(&sm.sT[k * ST_T16 + rr]) = make_float4(a0, a1, a2, a3);
        }
        const float* SO = states_o + (size_t)b * 32 * 128;
#pragma unroll
        for (int h = 0; h < 32; h += 16) {
            float a0 = SO[(rr + h + 0) * 128 + k];
            float a1 = SO[(rr + h + 1) * 128 + k];
            float a2 = SO[(rr + h + 2) * 128 + k];
            float a3 = SO[(rr + h + 3) * 128 + k];
            *reinterpret_cast<float4*>(&sm.oaoT[k * ST_T32 + rr + h]) = make_float4(a0, a1, a2, a3);
        }
        if (tid < 256) {
            int kk8 = tid >> 5, m = tid & 31;
            sm.oaoT[(128 + kk8) * ST_T32 + m] = actions_o[(size_t)b * 32 * 8 + m * 8 + kk8];
        }
        if (tid < 128) {
            int r = tid >> 3, c = tid & 7;
            sm.act[r * 8 + c] = actions[(size_t)b * 16 * 8 + r * 8 + c];
            sm.pol[r * 8 + c] = policies[(size_t)b * 16 * 8 + r * 8 + c];
        }
        if (tid < 64) sm.w2v[tid] = W2[tid];
    }

    // Prefetch (depth 4) BEFORE the barrier — ungated warps only
    float2 wA, wB, wC, wD;
    if (cls != 0) {
        wA = ldw(koff + 0); wB = ldw(koff + 1); wC = ldw(koff + 2); wD = ldw(koff + 3);
    }

    __syncthreads();

    // Gate: warps 0-7 wait for gg grid (PDL), then prefetch G rows
    if (cls == 0) {
        cudaGridDependencySynchronize();
        wA = ldw(koff + 0); wB = ldw(koff + 1); wC = ldw(koff + 2); wD = ldw(koff + 3);
    }

    // ---------- Stage 1 (unified 16-row x 2-col GEMM, raw outputs) ----------
    {
        u64 acc[2][8];
#pragma unroll
        for (int j = 0; j < 2; j++)
#pragma unroll
            for (int p = 0; p < 8; p++) acc[j][p] = 0ull;

        auto step = [&](int k, float2 w2) {
            const float* Ak = Abase + k * astride + r0;
            const ulonglong2 A0 = *reinterpret_cast<const ulonglong2*>(Ak);
            const ulonglong2 A1 = *reinterpret_cast<const ulonglong2*>(Ak + 4);
            const ulonglong2 A2 = *reinterpret_cast<const ulonglong2*>(Ak + 8);
            const ulonglong2 A3 = *reinterpret_cast<const ulonglong2*>(Ak + 12);
            const u64 wp0 = pack2(w2.x, w2.x);
            const u64 wp1 = pack2(w2.y, w2.y);
            acc[0][0] = fma2(A0.x, wp0, acc[0][0]);
            acc[0][1] = fma2(A0.y, wp0, acc[0][1]);
            acc[0][2] = fma2(A1.x, wp0, acc[0][2]);
            acc[0][3] = fma2(A1.y, wp0, acc[0][3]);
            acc[0][4] = fma2(A2.x, wp0, acc[0][4]);
            acc[0][5] = fma2(A2.y, wp0, acc[0][5]);
            acc[0][6] = fma2(A3.x, wp0, acc[0][6]);
            acc[0][7] = fma2(A3.y, wp0, acc[0][7]);
            acc[1][0] = fma2(A0.x, wp1, acc[1][0]);
            acc[1][1] = fma2(A0.y, wp1, acc[1][1]);
            acc[1][2] = fma2(A1.x, wp1, acc[1][2]);
            acc[1][3] = fma2(A1.y, wp1, acc[1][3]);
            acc[1][4] = fma2(A2.x, wp1, acc[1][4]);
            acc[1][5] = fma2(A2.y, wp1, acc[1][5]);
            acc[1][6] = fma2(A3.x, wp1, acc[1][6]);
            acc[1][7] = fma2(A3.y, wp1, acc[1][7]);
        };

        step(koff + 0, wA);
        step(koff + 1, wB);
        step(koff + 2, wC);
        step(koff + 3, wD);
#pragma unroll 4
        for (int k = koff + 4; k < kend; k++) step(k, ldw(k));
#pragma unroll 4
        for (int k = kbeg; k < koff; k++) step(k, ldw(k));

        if (cls == 1) {
            // row-major t-quarter
#pragma unroll
            for (int p = 0; p < 8; p++) {
                float x0, y0, x1, y1;
                unpack2(acc[0][p], x0, y0);
                unpack2(acc[1][p], x1, y1);
                *reinterpret_cast<float2*>(&tq[(2 * p + 0) * ST_RM + col]) = make_float2(x0, x1);
                *reinterpret_cast<float2*>(&tq[(2 * p + 1) * ST_RM + col]) = make_float2(y0, y1);
            }
        } else {
            const int ostride = (cls == 0) ? ST_T16 : ST_T32;
#pragma unroll
            for (int j = 0; j < 2; j++) {
                float* d = outp + (col + j) * ostride + r0;
                ulonglong2 s0 = {acc[j][0], acc[j][1]};
                ulonglong2 s1 = {acc[j][2], acc[j][3]};
                ulonglong2 s2 = {acc[j][4], acc[j][5]};
                ulonglong2 s3 = {acc[j][6], acc[j][7]};
                *reinterpret_cast<ulonglong2*>(d)      = s0;
                *reinterpret_cast<ulonglong2*>(d + 4)  = s1;
                *reinterpret_cast<ulonglong2*>(d + 8)  = s2;
                *reinterpret_cast<ulonglong2*>(d + 12) = s3;
            }
        }
    }
    __syncthreads();

    // ---------- Stage 1.5: combines + tanh + avact/delta tails ----------
    {
        float2* dy = reinterpret_cast<float2*>(sm.YTa);
        const float2* sy = reinterpret_cast<const float2*>(sm.YTb);
        for (int idx = tid; idx < 1280; idx += 768) {
            float2 a = dy[idx], c = sy[idx];
            dy[idx] = make_float2(a.x + c.x, a.y + c.y);
        }
        float2* dz = reinterpret_cast<float2*>(sm.YoTa);
        const float2* sz = reinterpret_cast<const float2*>(sm.YoTb);
        for (int idx = tid; idx < 1280; idx += 768) {
            float2 a = dz[idx], c = sz[idx];
            dz[idx] = make_float2(a.x + c.x, a.y + c.y);
        }
        float2* da = reinterpret_cast<float2*>(sm.avoTa);
        const float2* sa = reinterpret_cast<const float2*>(sm.avoTb);
        for (int idx = tid; idx < 2304; idx += 768) {
            float2 a = da[idx], c = sa[idx];
            da[idx] = make_float2(fast_tanh(a.x + c.x), fast_tanh(a.y + c.y));
        }
        // tails: 2048 (r,c) items
        for (int idx = tid; idx < 2048; idx += 768) {
            const int r = idx & 15, c = idx >> 4;
            float tv = sm.t0[r * ST_RM + c] + sm.t1[r * ST_RM + c]
                     + sm.t2[r * ST_RM + c] + sm.t3[r * ST_RM + c];
            float aa = tv, ap = tv;
#pragma unroll
            for (int k = 0; k < 8; k++) {
                const float wv = Wv[(128 + k) * 128 + c];
                aa = fmaf(sm.act[r * 8 + k], wv, aa);
                ap = fmaf(sm.pol[r * 8 + k], wv, ap);
            }
            const float ta = fast_tanh(aa);
            sm.avactT[c * ST_T16 + r] = ta;
            sm.deltaT[c * ST_T16 + r] = fast_tanh(ap) - ta;
        }
    }
    __syncthreads();

    // ---------- Stage 2: attention scores (k-split x2 + shuffle reduce) ----------
    const float scale = 0.08838834764831845f;  // 1/sqrt(128)
    if (tid < 256) {
        const int pr = tid >> 1, khf = tid & 1;
        const int i = pr >> 3, j2 = pr & 7;
        const int k0 = khf * 64;
        u64 a0 = 0ull, a1 = 0ull;
#pragma unroll 4
        for (int k = k0; k < k0 + 64; k += 2) {
            const float q0 = sm.YTa[(k + 0) * ST_T16 + i];
            const float q1 = sm.YTa[(k + 1) * ST_T16 + i];
            const u64 kp0 = *reinterpret_cast<const u64*>(&sm.sT[(k + 0) * ST_T16 + 2 * j2]);
            const u64 kp1 = *reinterpret_cast<const u64*>(&sm.sT[(k + 1) * ST_T16 + 2 * j2]);
            a0 = fma2(pack2(q0, q0), kp0, a0);
            a1 = fma2(pack2(q1, q1), kp1, a1);
        }
        float s0, s1, t0v, t1v;
        unpack2(a0, s0, s1);
        unpack2(a1, t0v, t1v);
        float p0 = s0 + t0v, p1 = s1 + t1v;
        p0 += __shfl_xor_sync(0xffffffffu, p0, 1);
        p1 += __shfl_xor_sync(0xffffffffu, p1, 1);
        if (khf == 0)
            *reinterpret_cast<float2*>(&sm.w[i * 16 + 2 * j2]) =
                make_float2(p0 * scale, p1 * scale);
    } else {
        const int t2i = tid - 256;
        const int pr = t2i >> 1, khf = t2i & 1;
        const int i = pr >> 4, m2 = pr & 15;
        const int k0 = khf * 64;
        u64 a0 = 0ull, a1 = 0ull;
#pragma unroll 4
        for (int k = k0; k < k0 + 64; k += 2) {
            const float q0 = sm.YoTa[(k + 0) * ST_T16 + i];
            const float q1 = sm.YoTa[(k + 1) * ST_T16 + i];
            const u64 kp0 = *reinterpret_cast<const u64*>(&sm.oaoT[(k + 0) * ST_T32 + 2 * m2]);
            const u64 kp1 = *reinterpret_cast<const u64*>(&sm.oaoT[(k + 1) * ST_T32 + 2 * m2]);
            a0 = fma2(pack2(q0, q0), kp0, a0);
            a1 = fma2(pack2(q1, q1), kp1, a1);
        }
        float s0, s1, t0v, t1v;
        unpack2(a0, s0, s1);
        unpack2(a1, t0v, t1v);
        float p0 = s0 + t0v, p1 = s1 + t1v;
        p0 += __shfl_xor_sync(0xffffffffu, p0, 1);
        p1 += __shfl_xor_sync(0xffffffffu, p1, 1);
        if (khf == 0)
            *reinterpret_cast<float2*>(&sm.wo[i * 32 + 2 * m2]) =
                make_float2(p0 * scale, p1 * scale);
    }

    // ---------- Stage-3 config + prefetch (before barrier) ----------
    const float* AT;
    const float* Wg;
    float* dst3;
    int r03, strideA3, col3, kbeg3, kend3, koff3;
    if (tid < 256) {
        // P = avact@W1a, v = delta@W1a : full k
        const int cq2 = tid & 31;
        const int rg  = tid >> 5;
        col3 = cq2 * 2;
        AT   = (rg < 4 ? sm.avactT : sm.deltaT);
        r03  = (rg & 3) * 4;
        strideA3 = ST_T16;
        Wg   = W1;
        dst3 = (rg < 4 ? sm.P : sm.v);
        kbeg3 = 0; kend3 = 128;
        koff3 = (rg & 7) * 16;
    } else {
        // X = avo@W1b : k-halved across two thread-groups
        const int t3i = tid - 256;
        const int kh3 = t3i >> 8;
        const int t4 = t3i & 255;
        const int cq2 = t4 & 31;
        const int rg  = t4 >> 5;
        col3 = cq2 * 2;
        AT   = sm.avoTa;
        r03  = rg * 4;
        strideA3 = ST_T32;
        Wg   = W1 + 128 * 64;
        dst3 = kh3 ? sm.X2 : sm.X;
        kbeg3 = kh3 * 64; kend3 = kbeg3 + 64;
        koff3 = kbeg3 + (rg & 7) * 8;
    }
    auto ldw3 = [&](int k){ return *reinterpret_cast<const float2*>(Wg + k * 64 + col3); };
    float2 pA = ldw3(koff3 + 0), pB = ldw3(koff3 + 1), pC = ldw3(koff3 + 2), pD = ldw3(koff3 + 3);

    __syncthreads();

    // ---------- Stage 3: softmaxes + P/v/X GEMMs ----------
    if (tid < 16) {
        const int i = tid;
        float mx = -1e30f;
#pragma unroll
        for (int j = 0; j < 16; j++) mx = fmaxf(mx, sm.w[i * 16 + j]);
        float s = 0.f, e[16];
#pragma unroll
        for (int j = 0; j < 16; j++) { e[j] = __expf(sm.w[i * 16 + j] - mx); s += e[j]; }
        const float inv = __fdividef(1.f, s);
#pragma unroll
        for (int j = 0; j < 16; j++) {
            float p = e[j] * inv;
            sm.w[i * 16 + j] = p;
            out_w[(size_t)b * 256 + i * 16 + j] = p;
        }
    } else if (tid < 48) {
        const int m = tid - 16;
        float mx = -1e30f;
#pragma unroll
        for (int i = 0; i < 16; i++) mx = fmaxf(mx, sm.wo[i * 32 + m]);
        float s = 0.f, e[16];
#pragma unroll
        for (int i = 0; i < 16; i++) { e[i] = __expf(sm.wo[i * 32 + m] - mx); s += e[i]; }
        const float inv = __fdividef(1.f, s);
#pragma unroll
        for (int i = 0; i < 16; i++) {
            float p = e[i] * inv;
            sm.wo[i * 32 + m] = p;
            out_wo[(size_t)b * 512 + i * 32 + m] = p;
        }
    }
    {
        u64 a00 = 0ull, a01 = 0ull, a10 = 0ull, a11 = 0ull;
        auto step3 = [&](int k, float2 wv) {
            const ulonglong2 A = *reinterpret_cast<const ulonglong2*>(&AT[k * strideA3 + r03]);
            const u64 wp0 = pack2(wv.x, wv.x);
            const u64 wp1 = pack2(wv.y, wv.y);
            a00 = fma2(A.x, wp0, a00);
            a01 = fma2(A.y, wp0, a01);
            a10 = fma2(A.x, wp1, a10);
            a11 = fma2(A.y, wp1, a11);
        };
        step3(koff3 + 0, pA);
        step3(koff3 + 1, pB);
        step3(koff3 + 2, pC);
        step3(koff3 + 3, pD);
#pragma unroll 4
        for (int k = koff3 + 4; k < kend3; k++) step3(k, ldw3(k));
#pragma unroll 4
        for (int k = kbeg3; k < koff3; k++) step3(k, ldw3(k));

        float x0, x1, x2, x3, y0, y1, y2, y3;
        unpack2(a00, x0, x1); unpack2(a01, x2, x3);
        unpack2(a10, y0, y1); unpack2(a11, y2, y3);
        *reinterpret_cast<float2*>(&dst3[(r03 + 0) * ST_PX + col3]) = make_float2(x0, y0);
        *reinterpret_cast<float2*>(&dst3[(r03 + 1) * ST_PX + col3]) = make_float2(x1, y1);
        *reinterpret_cast<float2*>(&dst3[(r03 + 2) * ST_PX + col3]) = make_float2(x2, y2);
        *reinterpret_cast<float2*>(&dst3[(r03 + 3) * ST_PX + col3]) = make_float2(x3, y3);
    }
    __syncthreads();

    // ---------- Stage 5: u = w @ P + wo @ (X + X2) ----------
    for (int idx = tid; idx < 1024; idx += 768) {
        const int i = idx >> 6;
        const int c = idx & 63;
        float acc0 = 0.f, acc1 = 0.f;
#pragma unroll
        for (int j = 0; j < 16; j += 2) {
            acc0 = fmaf(sm.w[i * 16 + j],     sm.P[j * ST_PX + c],       acc0);
            acc1 = fmaf(sm.w[i * 16 + j + 1], sm.P[(j + 1) * ST_PX + c], acc1);
        }
#pragma unroll
        for (int m = 0; m < 32; m += 2) {
            const float xv0 = sm.X[m * ST_PX + c]       + sm.X2[m * ST_PX + c];
            const float xv1 = sm.X[(m + 1) * ST_PX + c] + sm.X2[(m + 1) * ST_PX + c];
            acc0 = fmaf(sm.wo[i * 32 + m],     xv0, acc0);
            acc1 = fmaf(sm.wo[i * 32 + m + 1], xv1, acc1);
        }
        sm.u[i * ST_PX + c] = acc0 + acc1;
    }
    __syncthreads();

    // ---------- Stage 6: final value (threads 0-511) ----------
    if (tid < 512) {
        const int p = tid >> 1, h = tid & 1;
        const int i = p >> 4, j = p & 15;
        const float wt = sm.w[i * 16 + j];
        float acc0 = 0.f, acc1 = 0.f;
        const int d0 = h * 32;
#pragma unroll
        for (int d = d0; d < d0 + 32; d += 2) {
            float h0 = fmaf(wt, sm.v[j * ST_PX + d],     sm.u[i * ST_PX + d]);
            float h1 = fmaf(wt, sm.v[j * ST_PX + d + 1], sm.u[i * ST_PX + d + 1]);
            h0 = fmaxf(h0, 0.01f * h0);
            h1 = fmaxf(h1, 0.01f * h1);
            acc0 = fmaf(h0, sm.w2v[d],     acc0);
            acc1 = fmaf(h1, sm.w2v[d + 1], acc1);
        }
        float acc = acc0 + acc1;
        acc += __shfl_xor_sync(0xffffffffu, acc, 1);
        if (h == 0) out_value[(size_t)b * 256 + p] = acc;
    }
}

extern "C" void kernel_launch(void* const* d_in, const int* in_sizes, int n_in,
                              void* d_out, int out_size) {
    const float* states    = (const float*)d_in[0];
    const float* policies  = (const float*)d_in[1];
    const float* actions   = (const float*)d_in[2];
    const float* states_o  = (const float*)d_in[3];
    const float* actions_o = (const float*)d_in[4];
    const float* Wk  = (const float*)d_in[5];
    const float* Wq  = (const float*)d_in[6];
    const float* Wv  = (const float*)d_in[7];
    const float* Wko = (const float*)d_in[8];
    const float* Wqo = (const float*)d_in[9];
    const float* Wvo = (const float*)d_in[10];
    const float* W1  = (const float*)d_in[11];
    const float* W2  = (const float*)d_in[12];

    float* out       = (float*)d_out;
    float* out_value = out;                    // [B,N,N,1]
    float* out_w     = out + BB * 256;         // [B,N,N]
    float* out_wo    = out + 2 * BB * 256;     // [B,N,M,1]

    cudaFuncSetAttribute(critic_kernel,
                         cudaFuncAttributeMaxDynamicSharedMemorySize,
                         (int)sizeof(Smem));
    cudaFuncSetAttribute(gg_kernel,
                         cudaFuncAttributeMaxDynamicSharedMemorySize,
                         (int)GG_SMEM);

    // Primary: gg (16 CTAs; 16 + 128 = 144 <= 148 SMs, single co-resident wave)
    gg_kernel<<<16, 512, GG_SMEM>>>(Wq, Wk, Wqo, Wko);

    // Secondary: critic (768 threads) with programmatic dependent launch
    cudaLaunchConfig_t cfg = {};
    cfg.gridDim = dim3(BB, 1, 1);
    cfg.blockDim = dim3(768, 1, 1);
    cfg.dynamicSmemBytes = sizeof(Smem);
    cudaLaunchAttribute attrs[1];
    attrs[0].id = cudaLaunchAttributeProgrammaticStreamSerialization;
    attrs[0].val.programmaticStreamSerializationAllowed = 1;
    cfg.attrs = attrs;
    cfg.numAttrs = 1;

    cudaLaunchKernelEx(&cfg, critic_kernel,
                       states, policies, actions, states_o, actions_o,
                       Wv, Wvo, W1, W2, out_value, out_w, out_wo);
}

// round 16
// speedup vs baseline: 1.2119x; 1.2119x over previous
#include <cuda_runtime.h>

#define BB 128
typedef unsigned long long u64;

__device__ __forceinline__ u64 pack2(float x, float y){
    u64 r; asm("mov.b64 %0,{%1,%2};" : "=l"(r) : "f"(x), "f"(y)); return r;
}
__device__ __forceinline__ void unpack2(u64 a, float& x, float& y){
    asm("mov.b64 {%0,%1},%2;" : "=f"(x), "=f"(y) : "l"(a));
}
__device__ __forceinline__ u64 fma2(u64 a, u64 b, u64 c){
    u64 d; asm("fma.rn.f32x2 %0,%1,%2,%3;" : "=l"(d) : "l"(a), "l"(b), "l"(c)); return d;
}
__device__ __forceinline__ float fast_tanh(float x){
    float e = __expf(2.0f * x);
    return 1.0f - __fdividef(2.0f, e + 1.0f);
}

// Folded score matrices (recomputed every launch by gg_kernel -> deterministic)
__device__ float Gd [128 * 128];   // Wq  @ Wk^T
__device__ float God[128 * 128];   // Wqo @ Wko^T

// ============ Precompute kernel: verbatim from passing R14 ============
#define GG_AT   (128 * 18)
#define GG_BT   (128 * 66)
#define GG_SMEM ((GG_AT + 2 * GG_BT) * sizeof(float))

__global__ __launch_bounds__(512, 1)
void gg_kernel(const float* __restrict__ Wq,  const float* __restrict__ Wk,
               const float* __restrict__ Wqo, const float* __restrict__ Wko)
{
    cudaTriggerProgrammaticLaunchCompletion();

    extern __shared__ float gg_sm[];
    float* aT  = gg_sm;
    float* bTa = gg_sm + GG_AT;
    float* bTb = bTa + GG_BT;

    const int tid = threadIdx.x;
    const int cta = blockIdx.x;          // 0..15
    const bool second = cta >= 8;
    const int d0 = (cta & 7) * 16;
    const float* Wa = second ? Wqo : Wq;
    const float* Wb = second ? Wko : Wk;
    float* Gout = second ? God : Gd;

    for (int idx = tid; idx < 16 * 128; idx += 512) {
        int r = idx >> 7, a = idx & 127;
        aT[a * 18 + r] = Wa[(d0 + r) * 128 + a];
    }
    for (int idx = tid; idx < 64 * 128; idx += 512) {
        int e = idx >> 7, a = idx & 127;
        bTa[a * 66 + e] = Wb[e * 128 + a];
        bTb[a * 66 + e] = Wb[(64 + e) * 128 + a];
    }
    __syncthreads();

    const int half = tid >> 8;
    const int t2   = tid & 255;
    const int e2 = t2 & 31;
    const int rg = t2 >> 5;
    const float* bT = half ? bTb : bTa;
    const int e0 = half * 64;

    u64 acc0 = 0ull, acc1 = 0ull;
#pragma unroll 4
    for (int a = 0; a < 128; a++) {
        const u64 we = *reinterpret_cast<const u64*>(&bT[a * 66 + 2 * e2]);
        const float2 ar = *reinterpret_cast<const float2*>(&aT[a * 18 + 2 * rg]);
        acc0 = fma2(pack2(ar.x, ar.x), we, acc0);
        acc1 = fma2(pack2(ar.y, ar.y), we, acc1);
    }
    float x0, x1, y0, y1;
    unpack2(acc0, x0, x1);
    unpack2(acc1, y0, y1);
    float* g0 = Gout + (d0 + 2 * rg) * 128 + e0 + 2 * e2;
    *reinterpret_cast<float2*>(g0)       = make_float2(x0, x1);
    *reinterpret_cast<float2*>(g0 + 128) = make_float2(y0, y1);
}

#define ST_T16 20
#define ST_T32 36
#define ST_RM  132
#define ST_PX  66

struct Smem {
    float sT    [128 * ST_T16];
    float oaoT  [136 * ST_T32];
    float act   [16 * 8];
    float pol   [16 * 8];
    float YTa   [128 * ST_T16];  // (s@G)^T  kh0
    float YTb   [128 * ST_T16];  //          kh1
    float YoTa  [128 * ST_T16];  // (s@Go)^T kh0
    float YoTb  [128 * ST_T16];  //          kh1
    float t0    [16 * ST_RM];    // s@Wv k-quarters (row-major)
    float t1    [16 * ST_RM];
    float t2    [16 * ST_RM];
    float t3    [16 * ST_RM];
    float avoT  [128 * ST_T32];
    float avactT[128 * ST_T16];
    float deltaT[128 * ST_T16];
    float w     [256];
    float wo    [512];
    float P     [16 * ST_PX];
    float X     [32 * ST_PX];
    float u     [16 * ST_PX];
    float v     [16 * ST_PX];
    float w2v   [64];
};

__global__ __launch_bounds__(512, 1)
void critic_kernel(const float* __restrict__ states,
                   const float* __restrict__ policies,
                   const float* __restrict__ actions,
                   const float* __restrict__ states_o,
                   const float* __restrict__ actions_o,
                   const float* __restrict__ Wv,
                   const float* __restrict__ Wvo,
                   const float* __restrict__ W1,  const float* __restrict__ W2,
                   float* __restrict__ out_value,
                   float* __restrict__ out_w,
                   float* __restrict__ out_wo)
{
    extern __shared__ unsigned char smem_raw[];
    Smem& sm = *reinterpret_cast<Smem*>(smem_raw);

    const int b    = blockIdx.x;
    const int tid  = threadIdx.x;
    const int warp = tid >> 5;
    const int lane = tid & 31;

    // ---------- Stage-1 config ----------
    // warps 0-7 (gated) : Y/Yo via G/Go, mat x kh x colh -> 64-k partials (1472 slots)
    // warps 8-15        : Wvo 8-row x colh full 136k (1781) + Wv 32-k quarter (736)
    int r0 = 0, kbeg, kend, koff, col, cls;
    const float* Wm;
    float* outp = nullptr;
    if (warp < 8) {
        cls = 0;
        const int mat  = warp >> 2;       // 0: G, 1: Go
        const int kh   = (warp >> 1) & 1;
        const int colh = warp & 1;
        col = colh * 64 + lane * 2;
        kbeg = kh * 64; kend = kbeg + 64;
        koff = kbeg + ((warp * 8) & 63);
        Wm = (mat ? God : Gd) + col;
        outp = mat ? (kh ? sm.YoTb : sm.YoTa) : (kh ? sm.YTb : sm.YTa);
    } else {
        cls = 2;
        const int wrp = warp - 8;
        r0 = (wrp >> 1) * 8;
        col = (wrp & 1) * 64 + lane * 2;
        kbeg = 0; kend = 136;
        koff = (wrp * 16 + 4) & 127;
        Wm = Wvo + col;
    }
    auto ldw = [&](int k){ return *reinterpret_cast<const float2*>(Wm + k * 128); };

    // ---------- Stage 0: load + transpose inputs ----------
    {
        const int k  = tid & 127;
        const int g  = tid >> 7;
        const int rr = g * 4;
        const float* S = states + (size_t)b * 16 * 128;
        {
            float a0 = S[(rr + 0) * 128 + k];
            float a1 = S[(rr + 1) * 128 + k];
            float a2 = S[(rr + 2) * 128 + k];
            float a3 = S[(rr + 3) * 128 + k];
            *reinterpret_cast<float4*>(&sm.sT[k * ST_T16 + rr]) = make_float4(a0, a1, a2, a3);
        }
        const float* SO = states_o + (size_t)b * 32 * 128;
#pragma unroll
        for (int h = 0; h < 32; h += 16) {
            float a0 = SO[(rr + h + 0) * 128 + k];
            float a1 = SO[(rr + h + 1) * 128 + k];
            float a2 = SO[(rr + h + 2) * 128 + k];
            float a3 = SO[(rr + h + 3) * 128 + k];
            *reinterpret_cast<float4*>(&sm.oaoT[k * ST_T32 + rr + h]) = make_float4(a0, a1, a2, a3);
        }
        if (tid < 256) {
            int kk8 = tid >> 5, m = tid & 31;
            sm.oaoT[(128 + kk8) * ST_T32 + m] = actions_o[(size_t)b * 32 * 8 + m * 8 + kk8];
        }
        if (tid < 128) {
            int r = tid >> 3, c = tid & 7;
            sm.act[r * 8 + c] = actions[(size_t)b * 16 * 8 + r * 8 + c];
            sm.pol[r * 8 + c] = policies[(size_t)b * 16 * 8 + r * 8 + c];
        }
        if (tid < 64) sm.w2v[tid] = W2[tid];
    }

    // Deep prefetch BEFORE the barrier — ungated warps (Wvo) only
    float2 wA, wB, wC, wD, wE, wF, wG, wH;
    if (cls != 0) {
        wA = ldw(koff + 0); wB = ldw(koff + 1); wC = ldw(koff + 2); wD = ldw(koff + 3);
        wE = ldw(koff + 4); wF = ldw(koff + 5); wG = ldw(koff + 6); wH = ldw(koff + 7);
    }

    __syncthreads();

    // Gate: warps 0-7 wait (PDL) for gg grid, then prefetch G rows
    if (cls == 0) {
        cudaGridDependencySynchronize();
        wA = ldw(koff + 0); wB = ldw(koff + 1); wC = ldw(koff + 2); wD = ldw(koff + 3);
        wE = ldw(koff + 4); wF = ldw(koff + 5); wG = ldw(koff + 6); wH = ldw(koff + 7);
    }

    // ---------- Stage 1 ----------
    if (cls == 0) {
        // Y/Yo half-k GEMM: 16 rows x 2 cols
        u64 acc[2][8];
#pragma unroll
        for (int j = 0; j < 2; j++)
#pragma unroll
            for (int p = 0; p < 8; p++) acc[j][p] = 0ull;

        auto step = [&](int k, float2 w2) {
            const float* Ak = sm.sT + k * ST_T16;
            const ulonglong2 A0 = *reinterpret_cast<const ulonglong2*>(Ak);
            const ulonglong2 A1 = *reinterpret_cast<const ulonglong2*>(Ak + 4);
            const ulonglong2 A2 = *reinterpret_cast<const ulonglong2*>(Ak + 8);
            const ulonglong2 A3 = *reinterpret_cast<const ulonglong2*>(Ak + 12);
            const u64 wp0 = pack2(w2.x, w2.x);
            const u64 wp1 = pack2(w2.y, w2.y);
            acc[0][0] = fma2(A0.x, wp0, acc[0][0]);
            acc[0][1] = fma2(A0.y, wp0, acc[0][1]);
            acc[0][2] = fma2(A1.x, wp0, acc[0][2]);
            acc[0][3] = fma2(A1.y, wp0, acc[0][3]);
            acc[0][4] = fma2(A2.x, wp0, acc[0][4]);
            acc[0][5] = fma2(A2.y, wp0, acc[0][5]);
            acc[0][6] = fma2(A3.x, wp0, acc[0][6]);
            acc[0][7] = fma2(A3.y, wp0, acc[0][7]);
            acc[1][0] = fma2(A0.x, wp1, acc[1][0]);
            acc[1][1] = fma2(A0.y, wp1, acc[1][1]);
            acc[1][2] = fma2(A1.x, wp1, acc[1][2]);
            acc[1][3] = fma2(A1.y, wp1, acc[1][3]);
            acc[1][4] = fma2(A2.x, wp1, acc[1][4]);
            acc[1][5] = fma2(A2.y, wp1, acc[1][5]);
            acc[1][6] = fma2(A3.x, wp1, acc[1][6]);
            acc[1][7] = fma2(A3.y, wp1, acc[1][7]);
        };

        step(koff + 0, wA);
        step(koff + 1, wB);
        step(koff + 2, wC);
        step(koff + 3, wD);
        step(koff + 4, wE);
        step(koff + 5, wF);
        step(koff + 6, wG);
        step(koff + 7, wH);
#pragma unroll 8
        for (int k = koff + 8; k < kend; k++) step(k, ldw(k));
#pragma unroll 8
        for (int k = kbeg; k < koff; k++) step(k, ldw(k));

#pragma unroll
        for (int j = 0; j < 2; j++) {
            float* d = outp + (col + j) * ST_T16;
            ulonglong2 s0 = {acc[j][0], acc[j][1]};
            ulonglong2 s1 = {acc[j][2], acc[j][3]};
            ulonglong2 s2 = {acc[j][4], acc[j][5]};
            ulonglong2 s3 = {acc[j][6], acc[j][7]};
            *reinterpret_cast<ulonglong2*>(d)      = s0;
            *reinterpret_cast<ulonglong2*>(d + 4)  = s1;
            *reinterpret_cast<ulonglong2*>(d + 8)  = s2;
            *reinterpret_cast<ulonglong2*>(d + 12) = s3;
        }
    } else {
        // Wvo: 8 rows x 2 cols, 136 k-steps, tanh epilogue
        u64 acc[2][4];
#pragma unroll
        for (int j = 0; j < 2; j++)
#pragma unroll
            for (int p = 0; p < 4; p++) acc[j][p] = 0ull;

        auto stepo = [&](int k, float2 w2) {
            const float* Ak = sm.oaoT + k * ST_T32 + r0;
            const ulonglong2 A0 = *reinterpret_cast<const ulonglong2*>(Ak);
            const ulonglong2 A1 = *reinterpret_cast<const ulonglong2*>(Ak + 4);
            const u64 wp0 = pack2(w2.x, w2.x);
            const u64 wp1 = pack2(w2.y, w2.y);
            acc[0][0] = fma2(A0.x, wp0, acc[0][0]);
            acc[0][1] = fma2(A0.y, wp0, acc[0][1]);
            acc[0][2] = fma2(A1.x, wp0, acc[0][2]);
            acc[0][3] = fma2(A1.y, wp0, acc[0][3]);
            acc[1][0] = fma2(A0.x, wp1, acc[1][0]);
            acc[1][1] = fma2(A0.y, wp1, acc[1][1]);
            acc[1][2] = fma2(A1.x, wp1, acc[1][2]);
            acc[1][3] = fma2(A1.y, wp1, acc[1][3]);
        };

        stepo(koff + 0, wA);
        stepo(koff + 1, wB);
        stepo(koff + 2, wC);
        stepo(koff + 3, wD);
        stepo(koff + 4, wE);
        stepo(koff + 5, wF);
        stepo(koff + 6, wG);
        stepo(koff + 7, wH);
#pragma unroll 8
        for (int k = koff + 8; k < 136; k++) stepo(k, ldw(k));
#pragma unroll 8
        for (int k = 0; k < koff; k++) stepo(k, ldw(k));

#pragma unroll
        for (int j = 0; j < 2; j++) {
            float t0_, t1_, t2_, t3_, t4_, t5_, t6_, t7_;
            unpack2(acc[j][0], t0_, t1_);
            unpack2(acc[j][1], t2_, t3_);
            unpack2(acc[j][2], t4_, t5_);
            unpack2(acc[j][3], t6_, t7_);
            float* d = sm.avoT + (col + j) * ST_T32 + r0;
            *reinterpret_cast<float4*>(d)     = make_float4(fast_tanh(t0_), fast_tanh(t1_), fast_tanh(t2_), fast_tanh(t3_));
            *reinterpret_cast<float4*>(d + 4) = make_float4(fast_tanh(t4_), fast_tanh(t5_), fast_tanh(t6_), fast_tanh(t7_));
        }

        // ---- Wv quarter-chunk: 16 rows x 2 cols over 32 k-steps ----
        {
            const int wrp  = warp - 8;
            const int colv = (wrp & 1) * 64 + lane * 2;
            const int kq   = wrp >> 1;            // 0..3
            const int kb   = kq * 32, ke = kb + 32;
            const float* Wmv = Wv + colv;
            float* tq = (kq == 0 ? sm.t0 : kq == 1 ? sm.t1 : kq == 2 ? sm.t2 : sm.t3);

            u64 av[2][8];
#pragma unroll
            for (int j = 0; j < 2; j++)
#pragma unroll
                for (int p = 0; p < 8; p++) av[j][p] = 0ull;

#pragma unroll 8
            for (int k = kb; k < ke; k++) {
                const float2 w2 = *reinterpret_cast<const float2*>(Wmv + k * 128);
                const float* Ak = sm.sT + k * ST_T16;
                const ulonglong2 A0 = *reinterpret_cast<const ulonglong2*>(Ak);
                const ulonglong2 A1 = *reinterpret_cast<const ulonglong2*>(Ak + 4);
                const ulonglong2 A2 = *reinterpret_cast<const ulonglong2*>(Ak + 8);
                const ulonglong2 A3 = *reinterpret_cast<const ulonglong2*>(Ak + 12);
                const u64 wp0 = pack2(w2.x, w2.x);
                const u64 wp1 = pack2(w2.y, w2.y);
                av[0][0] = fma2(A0.x, wp0, av[0][0]);
                av[0][1] = fma2(A0.y, wp0, av[0][1]);
                av[0][2] = fma2(A1.x, wp0, av[0][2]);
                av[0][3] = fma2(A1.y, wp0, av[0][3]);
                av[0][4] = fma2(A2.x, wp0, av[0][4]);
                av[0][5] = fma2(A2.y, wp0, av[0][5]);
                av[0][6] = fma2(A3.x, wp0, av[0][6]);
                av[0][7] = fma2(A3.y, wp0, av[0][7]);
                av[1][0] = fma2(A0.x, wp1, av[1][0]);
                av[1][1] = fma2(A0.y, wp1, av[1][1]);
                av[1][2] = fma2(A1.x, wp1, av[1][2]);
                av[1][3] = fma2(A1.y, wp1, av[1][3]);
                av[1][4] = fma2(A2.x, wp1, av[1][4]);
                av[1][5] = fma2(A2.y, wp1, av[1][5]);
                av[1][6] = fma2(A3.x, wp1, av[1][6]);
                av[1][7] = fma2(A3.y, wp1, av[1][7]);
            }
#pragma unroll
            for (int p = 0; p < 8; p++) {
                float x0, y0, x1, y1;
                unpack2(av[0][p], x0, y0);
                unpack2(av[1][p], x1, y1);
                *reinterpret_cast<float2*>(&tq[(2 * p + 0) * ST_RM + colv]) = make_float2(x0, x1);
                *reinterpret_cast<float2*>(&tq[(2 * p + 1) * ST_RM + colv]) = make_float2(y0, y1);
            }
        }
    }
    __syncthreads();

    // ---------- Stage 2: avactT/deltaT tails + attention scores ----------
    {
        const int g  = tid >> 7;
        const int c  = tid & 127;
        const int rr = g * 4;
        float aa[4], ap[4];
#pragma unroll
        for (int i = 0; i < 4; i++) {
            float tv = sm.t0[(rr + i) * ST_RM + c] + sm.t1[(rr + i) * ST_RM + c]
                     + sm.t2[(rr + i) * ST_RM + c] + sm.t3[(rr + i) * ST_RM + c];
            aa[i] = tv; ap[i] = tv;
        }
#pragma unroll
        for (int k = 0; k < 8; k++) {
            float wv = Wv[(128 + k) * 128 + c];
#pragma unroll
            for (int i = 0; i < 4; i++) {
                aa[i] = fmaf(sm.act[(rr + i) * 8 + k], wv, aa[i]);
                ap[i] = fmaf(sm.pol[(rr + i) * 8 + k], wv, ap[i]);
            }
        }
        float ta[4], dl[4];
#pragma unroll
        for (int i = 0; i < 4; i++) {
            ta[i] = fast_tanh(aa[i]);
            dl[i] = fast_tanh(ap[i]) - ta[i];
        }
        *reinterpret_cast<float4*>(&sm.avactT[c * ST_T16 + rr]) = make_float4(ta[0], ta[1], ta[2], ta[3]);
        *reinterpret_cast<float4*>(&sm.deltaT[c * ST_T16 + rr]) = make_float4(dl[0], dl[1], dl[2], dl[3]);
    }
    const float scale = 0.08838834764831845f;  // 1/sqrt(128)
    if (tid < 128) {
        // w[i][j] = (Ya+Yb)[i] . s[j]  (combine folded into the read)
        const int i = tid >> 3, j2 = tid & 7;
        u64 a0 = 0ull, a1 = 0ull;
#pragma unroll 4
        for (int k = 0; k < 128; k += 2) {
            const float q0 = sm.YTa[(k + 0) * ST_T16 + i] + sm.YTb[(k + 0) * ST_T16 + i];
            const float q1 = sm.YTa[(k + 1) * ST_T16 + i] + sm.YTb[(k + 1) * ST_T16 + i];
            const u64 kp0 = *reinterpret_cast<const u64*>(&sm.sT[(k + 0) * ST_T16 + 2 * j2]);
            const u64 kp1 = *reinterpret_cast<const u64*>(&sm.sT[(k + 1) * ST_T16 + 2 * j2]);
            a0 = fma2(pack2(q0, q0), kp0, a0);
            a1 = fma2(pack2(q1, q1), kp1, a1);
        }
        float s0, s1, t0v, t1v;
        unpack2(a0, s0, s1);
        unpack2(a1, t0v, t1v);
        *reinterpret_cast<float2*>(&sm.w[i * 16 + 2 * j2]) =
            make_float2((s0 + t0v) * scale, (s1 + t1v) * scale);
    } else if (tid < 384) {
        const int t2i = tid - 128;
        const int i = t2i >> 4, m2 = t2i & 15;
        u64 a0 = 0ull, a1 = 0ull;
#pragma unroll 4
        for (int k = 0; k < 128; k += 2) {
            const float q0 = sm.YoTa[(k + 0) * ST_T16 + i] + sm.YoTb[(k + 0) * ST_T16 + i];
            const float q1 = sm.YoTa[(k + 1) * ST_T16 + i] + sm.YoTb[(k + 1) * ST_T16 + i];
            const u64 kp0 = *reinterpret_cast<const u64*>(&sm.oaoT[(k + 0) * ST_T32 + 2 * m2]);
            const u64 kp1 = *reinterpret_cast<const u64*>(&sm.oaoT[(k + 1) * ST_T32 + 2 * m2]);
            a0 = fma2(pack2(q0, q0), kp0, a0);
            a1 = fma2(pack2(q1, q1), kp1, a1);
        }
        float s0, s1, t0v, t1v;
        unpack2(a0, s0, s1);
        unpack2(a1, t0v, t1v);
        *reinterpret_cast<float2*>(&sm.wo[i * 32 + 2 * m2]) =
            make_float2((s0 + t0v) * scale, (s1 + t1v) * scale);
    }

    // ---------- Stage-3 config + deep prefetch (before barrier) ----------
    const float* AT;
    const float* Wg;
    float* dst3;
    int r03, strideA3, col3;
    if (tid < 256) {
        const int cq2 = tid & 31;
        const int rg  = tid >> 5;
        col3 = cq2 * 2;
        AT   = (rg < 4 ? sm.avactT : sm.deltaT);
        r03  = (rg & 3) * 4;
        strideA3 = ST_T16;
        Wg   = W1;
        dst3 = (rg < 4 ? sm.P : sm.v);
    } else {
        const int tid2 = tid - 256;
        const int cq2 = tid2 & 31;
        const int rg  = tid2 >> 5;
        col3 = cq2 * 2;
        AT   = sm.avoT;
        r03  = rg * 4;
        strideA3 = ST_T32;
        Wg   = W1 + 128 * 64;
        dst3 = sm.X;
    }
    const int koff3 = ((tid >> 5) & 7) * 16;
    auto ldw3 = [&](int k){ return *reinterpret_cast<const float2*>(Wg + k * 64 + col3); };
    float2 pA = ldw3(koff3 + 0), pB = ldw3(koff3 + 1), pC = ldw3(koff3 + 2), pD = ldw3(koff3 + 3);
    float2 pE = ldw3(koff3 + 4), pF = ldw3(koff3 + 5), pG = ldw3(koff3 + 6), pH = ldw3(koff3 + 7);

    __syncthreads();

    // ---------- Stage 3: softmaxes + P/v/X GEMMs ----------
    if (tid < 16) {
        const int i = tid;
        float mx = -1e30f;
#pragma unroll
        for (int j = 0; j < 16; j++) mx = fmaxf(mx, sm.w[i * 16 + j]);
        float s = 0.f, e[16];
#pragma unroll
        for (int j = 0; j < 16; j++) { e[j] = __expf(sm.w[i * 16 + j] - mx); s += e[j]; }
        const float inv = __fdividef(1.f, s);
#pragma unroll
        for (int j = 0; j < 16; j++) {
            float p = e[j] * inv;
            sm.w[i * 16 + j] = p;
            out_w[(size_t)b * 256 + i * 16 + j] = p;
        }
    } else if (tid < 48) {
        const int m = tid - 16;
        float mx = -1e30f;
#pragma unroll
        for (int i = 0; i < 16; i++) mx = fmaxf(mx, sm.wo[i * 32 + m]);
        float s = 0.f, e[16];
#pragma unroll
        for (int i = 0; i < 16; i++) { e[i] = __expf(sm.wo[i * 32 + m] - mx); s += e[i]; }
        const float inv = __fdividef(1.f, s);
#pragma unroll
        for (int i = 0; i < 16; i++) {
            float p = e[i] * inv;
            sm.wo[i * 32 + m] = p;
            out_wo[(size_t)b * 512 + i * 32 + m] = p;
        }
    }
    {
        u64 a00 = 0ull, a01 = 0ull, a10 = 0ull, a11 = 0ull;
        auto step3 = [&](int k, float2 wv) {
            const ulonglong2 A = *reinterpret_cast<const ulonglong2*>(&AT[k * strideA3 + r03]);
            const u64 wp0 = pack2(wv.x, wv.x);
            const u64 wp1 = pack2(wv.y, wv.y);
            a00 = fma2(A.x, wp0, a00);
            a01 = fma2(A.y, wp0, a01);
            a10 = fma2(A.x, wp1, a10);
            a11 = fma2(A.y, wp1, a11);
        };
        step3(koff3 + 0, pA);
        step3(koff3 + 1, pB);
        step3(koff3 + 2, pC);
        step3(koff3 + 3, pD);
        step3(koff3 + 4, pE);
        step3(koff3 + 5, pF);
        step3(koff3 + 6, pG);
        step3(koff3 + 7, pH);
#pragma unroll 8
        for (int k = koff3 + 8; k < 128; k++) step3(k, ldw3(k));
#pragma unroll 8
        for (int k = 0; k < koff3; k++) step3(k, ldw3(k));

        float x0, x1, x2, x3, y0, y1, y2, y3;
        unpack2(a00, x0, x1); unpack2(a01, x2, x3);
        unpack2(a10, y0, y1); unpack2(a11, y2, y3);
        *reinterpret_cast<float2*>(&dst3[(r03 + 0) * ST_PX + col3]) = make_float2(x0, y0);
        *reinterpret_cast<float2*>(&dst3[(r03 + 1) * ST_PX + col3]) = make_float2(x1, y1);
        *reinterpret_cast<float2*>(&dst3[(r03 + 2) * ST_PX + col3]) = make_float2(x2, y2);
        *reinterpret_cast<float2*>(&dst3[(r03 + 3) * ST_PX + col3]) = make_float2(x3, y3);
    }
    __syncthreads();

    // ---------- Stage 5: u = w @ P + wo @ X ----------
    {
        const int i = tid >> 5;
        const int c = (tid & 31) * 2;
        float acc0 = 0.f, acc1 = 0.f, bcc0 = 0.f, bcc1 = 0.f;
#pragma unroll
        for (int j = 0; j < 16; j += 2) {
            const float wv0 = sm.w[i * 16 + j];
            const float wv1 = sm.w[i * 16 + j + 1];
            const float2 p0 = *reinterpret_cast<const float2*>(&sm.P[j * ST_PX + c]);
            const float2 p1 = *reinterpret_cast<const float2*>(&sm.P[(j + 1) * ST_PX + c]);
            acc0 = fmaf(wv0, p0.x, acc0);
            acc1 = fmaf(wv0, p0.y, acc1);
            bcc0 = fmaf(wv1, p1.x, bcc0);
            bcc1 = fmaf(wv1, p1.y, bcc1);
        }
#pragma unroll
        for (int m = 0; m < 32; m += 2) {
            const float wv0 = sm.wo[i * 32 + m];
            const float wv1 = sm.wo[i * 32 + m + 1];
            const float2 x0 = *reinterpret_cast<const float2*>(&sm.X[m * ST_PX + c]);
            const float2 x1 = *reinterpret_cast<const float2*>(&sm.X[(m + 1) * ST_PX + c]);
            acc0 = fmaf(wv0, x0.x, acc0);
            acc1 = fmaf(wv0, x0.y, acc1);
            bcc0 = fmaf(wv1, x1.x, bcc0);
            bcc1 = fmaf(wv1, x1.y, bcc1);
        }
        *reinterpret_cast<float2*>(&sm.u[i * ST_PX + c]) = make_float2(acc0 + bcc0, acc1 + bcc1);
    }
    __syncthreads();

    // ---------- Stage 6: final value ----------
    {
        const int p = tid >> 1, h = tid & 1;
        const int i = p >> 4, j = p & 15;
        const float wt = sm.w[i * 16 + j];
        float acc0 = 0.f, acc1 = 0.f;
        const int d0 = h * 32;
#pragma unroll
        for (int d = d0; d < d0 + 32; d += 2) {
            float h0 = fmaf(wt, sm.v[j * ST_PX + d],     sm.u[i * ST_PX + d]);
            float h1 = fmaf(wt, sm.v[j * ST_PX + d + 1], sm.u[i * ST_PX + d + 1]);
            h0 = fmaxf(h0, 0.01f * h0);
            h1 = fmaxf(h1, 0.01f * h1);
            acc0 = fmaf(h0, sm.w2v[d],     acc0);
            acc1 = fmaf(h1, sm.w2v[d + 1], acc1);
        }
        float acc = acc0 + acc1;
        acc += __shfl_xor_sync(0xffffffffu, acc, 1);
        if (h == 0) out_value[(size_t)b * 256 + p] = acc;
    }
}

extern "C" void kernel_launch(void* const* d_in, const int* in_sizes, int n_in,
                              void* d_out, int out_size) {
    const float* states    = (const float*)d_in[0];
    const float* policies  = (const float*)d_in[1];
    const float* actions   = (const float*)d_in[2];
    const float* states_o  = (const float*)d_in[3];
    const float* actions_o = (const float*)d_in[4];
    const float* Wk  = (const float*)d_in[5];
    const float* Wq  = (const float*)d_in[6];
    const float* Wv  = (const float*)d_in[7];
    const float* Wko = (const float*)d_in[8];
    const float* Wqo = (const float*)d_in[9];
    const float* Wvo = (const float*)d_in[10];
    const float* W1  = (const float*)d_in[11];
    const float* W2  = (const float*)d_in[12];

    float* out       = (float*)d_out;
    float* out_value = out;                    // [B,N,N,1]
    float* out_w     = out + BB * 256;         // [B,N,N]
    float* out_wo    = out + 2 * BB * 256;     // [B,N,M,1]

    cudaFuncSetAttribute(critic_kernel,
                         cudaFuncAttributeMaxDynamicSharedMemorySize,
                         (int)sizeof(Smem));
    cudaFuncSetAttribute(gg_kernel,
                         cudaFuncAttributeMaxDynamicSharedMemorySize,
                         (int)GG_SMEM);

    // Primary: gg (16 CTAs; 16 + 128 = 144 <= 148 SMs, single co-resident wave)
    gg_kernel<<<16, 512, GG_SMEM>>>(Wq, Wk, Wqo, Wko);

    // Secondary: critic with programmatic dependent launch
    cudaLaunchConfig_t cfg = {};
    cfg.gridDim = dim3(BB, 1, 1);
    cfg.blockDim = dim3(512, 1, 1);
    cfg.dynamicSmemBytes = sizeof(Smem);
    cudaLaunchAttribute attrs[1];
    attrs[0].id = cudaLaunchAttributeProgrammaticStreamSerialization;
    attrs[0].val.programmaticStreamSerializationAllowed = 1;
    cfg.attrs = attrs;
    cfg.numAttrs = 1;

    cudaLaunchKernelEx(&cfg, critic_kernel,
                       states, policies, actions, states_o, actions_o,
                       Wv, Wvo, W1, W2, out_value, out_w, out_wo);
}